// round 12
// baseline (speedup 1.0000x reference)
#include <cuda_runtime.h>

#define THREADS 1024
#define CTA_M   64
#define KT      16
#define HID     512
#define LAT     64
#define LNEPS   1e-5f
#define TSTRIDE 257
#define TILE_F  72

__device__ __forceinline__ unsigned f2tf(float f) {
    unsigned u;
    asm("cvt.rna.tf32.f32 %0, %1;" : "=r"(u) : "f"(f));
    return u;
}

__device__ __forceinline__ void mma8(float c[4], unsigned a0, unsigned a1, unsigned a2, unsigned a3,
                                     unsigned b0, unsigned b1) {
    asm volatile(
        "mma.sync.aligned.m16n8k8.row.col.f32.tf32.tf32.f32 "
        "{%0,%1,%2,%3},{%4,%5,%6,%7},{%8,%9},{%0,%1,%2,%3};\n"
        : "+f"(c[0]), "+f"(c[1]), "+f"(c[2]), "+f"(c[3])
        : "r"(a0), "r"(a1), "r"(a2), "r"(a3), "r"(b0), "r"(b1));
}

// ---- async weight staging (R5 tile layout): chunk = [kstep][ntile] tiles of
// TILE_F floats; element (kp,nc) at pos = kp*8 + (nc ^ (kp&4)).
// Each thread cp.asyncs one n-quad for rows rA and rA+4.
template<int N, bool HEADS>
__device__ __forceinline__ void cp_chunk(const float* __restrict__ Bg, float* buf, int k0, int tid) {
    int w = tid >> 5, lane = tid & 31;
    int kstep = w & 1, kr = (w >> 1) & 3, eighth = w >> 3;
    int nq = eighth * 32 + lane;
    if (N == 256 && nq >= 64) return;   // GEMM3 needs half the threads
    int n = nq << 2;
    int rA = k0 + kstep * 8 + kr;
    const float* pA;
    const float* pB;
    if (HEADS) {  // Wh1[4][HID][64], col n = head*64 + d
        pA = Bg + (n >> 6) * (HID * 64) + rA * 64 + (n & 63);
        pB = pA + 4 * 64;
    } else {
        pA = Bg + rA * N + n;
        pB = pA + 4 * N;
    }
    int nt = nq >> 1, nb = (nq & 1) * 4;
    float* tb = buf + (kstep * (N / 8) + nt) * TILE_F;
    unsigned d0 = (unsigned)__cvta_generic_to_shared(tb + kr * 8 + nb);
    unsigned d1 = (unsigned)__cvta_generic_to_shared(tb + (kr + 4) * 8 + (nb ^ 4));
    asm volatile("cp.async.cg.shared.global [%0], [%1], 16;\n" :: "r"(d0), "l"(pA));
    asm volatile("cp.async.cg.shared.global [%0], [%1], 16;\n" :: "r"(d1), "l"(pB));
}

// ---- mma over one staged chunk; warp = 2 m-tiles x (N/128) n-tiles ----
template<int N>
__device__ __forceinline__ void mma_chunk(const float* Asm, int astride, const float* buf,
                                          float (*acc)[4], int wm, int wn, int lane, int k0) {
    constexpr int NT = N / 128;
    int g = lane >> 2, t = lane & 3;
    int s = g << 2;
    #pragma unroll
    for (int ks = 0; ks < 2; ks++) {
        int kA = k0 + ks * 8 + t;
        unsigned a[2][4];
        #pragma unroll
        for (int mt = 0; mt < 2; mt++) {
            int row = wm * 32 + mt * 16 + g;
            a[mt][0] = __float_as_uint(Asm[row * astride + (kA ^ s)]);
            a[mt][1] = __float_as_uint(Asm[(row + 8) * astride + (kA ^ s)]);
            a[mt][2] = __float_as_uint(Asm[row * astride + ((kA + 4) ^ s)]);
            a[mt][3] = __float_as_uint(Asm[(row + 8) * astride + ((kA + 4) ^ s)]);
        }
        const float* tb = buf + (ks * (N / 8) + wn * NT) * TILE_F;
        #pragma unroll
        for (int nt = 0; nt < NT; nt++) {
            const float* tp = tb + nt * TILE_F;
            unsigned b0 = __float_as_uint(tp[t * 8 + g]);
            unsigned b1 = __float_as_uint(tp[(t + 4) * 8 + (g ^ 4)]);
            mma8(acc[nt],      a[0][0], a[0][1], a[0][2], a[0][3], b0, b1);
            mma8(acc[NT + nt], a[1][0], a[1][1], a[1][2], a[1][3], b0, b1);
        }
    }
}

template<int N, int KTOT, bool HEADS>
__device__ __forceinline__ void run_gemm(const float* Asm, int astride, const float* __restrict__ Bg,
                                         float* stage, float (*acc)[4], int tid) {
    constexpr int NC = KTOT / KT;
    constexpr int NT2 = 2 * (N / 128);
    constexpr int CHUNKF = 2 * (N / 8) * TILE_F;
    int warp = tid >> 5, lane = tid & 31;
    int wm = warp & 1, wn = warp >> 1;
    #pragma unroll
    for (int i = 0; i < NT2; i++) {
        #pragma unroll
        for (int j = 0; j < 4; j++) acc[i][j] = 0.f;
    }
    cp_chunk<N, HEADS>(Bg, stage, 0, tid);
    asm volatile("cp.async.commit_group;\n" ::: "memory");
    #pragma unroll 1
    for (int c = 0; c < NC; c++) {
        asm volatile("cp.async.wait_group 0;\n" ::: "memory");
        __syncthreads();
        if (c + 1 < NC) {
            cp_chunk<N, HEADS>(Bg, stage + ((c + 1) & 1) * CHUNKF, (c + 1) * KT, tid);
            asm volatile("cp.async.commit_group;\n" ::: "memory");
        }
        mma_chunk<N>(Asm, astride, stage + (c & 1) * CHUNKF, acc, wm, wn, lane, c * KT);
    }
    __syncthreads();
}

// store whole-N accumulators (N=512) into swizzled activation buffer
__device__ __forceinline__ void store_acc512(float (*acc)[4], float* sh, int tid) {
    int warp = tid >> 5, lane = tid & 31;
    int wm = warp & 1, wn = warp >> 1;
    int g = lane >> 2, t = lane & 3;
    int s = g << 2;
    #pragma unroll
    for (int mt = 0; mt < 2; mt++) {
        int row = wm * 32 + mt * 16 + g;
        #pragma unroll
        for (int nt = 0; nt < 4; nt++) {
            int col = wn * 32 + nt * 8 + 2 * t;
            int c0 = col ^ s;
            float* a = acc[mt * 4 + nt];
            *reinterpret_cast<float2*>(sh + row * HID + c0)       = make_float2(a[0], a[1]);
            *reinterpret_cast<float2*>(sh + (row + 8) * HID + c0) = make_float2(a[2], a[3]);
        }
    }
}

// in-place: h = leaky( LN(h + bias) * gamma + beta ), output rounded to tf32
__device__ __forceinline__ void layernorm_leaky(float* sh, const float* __restrict__ bias,
                                                const float* __restrict__ gam,
                                                const float* __restrict__ bet, int tid) {
    int warp = tid >> 5, lane = tid & 31;
    #pragma unroll 1
    for (int r0 = 0; r0 < 2; r0++) {
        int r = warp * 2 + r0;
        int s = (r & 7) << 2;
        float v[16];
        float sum = 0.f, sq = 0.f;
        #pragma unroll
        for (int j = 0; j < 16; j++) {
            int k = lane + 32 * j;
            float x = sh[r * HID + (k ^ s)] + __ldg(bias + k);
            v[j] = x;
            sum += x;
            sq = fmaf(x, x, sq);
        }
        #pragma unroll
        for (int o = 16; o > 0; o >>= 1) {
            sum += __shfl_xor_sync(0xffffffffu, sum, o);
            sq  += __shfl_xor_sync(0xffffffffu, sq,  o);
        }
        float mu = sum * (1.f / 512.f);
        float var = sq * (1.f / 512.f) - mu * mu;
        float rs = rsqrtf(var + LNEPS);
        #pragma unroll
        for (int j = 0; j < 16; j++) {
            int k = lane + 32 * j;
            float x = (v[j] - mu) * rs * __ldg(gam + k) + __ldg(bet + k);
            x = (x >= 0.f) ? x : 0.2f * x;
            sh[r * HID + (k ^ s)] = __uint_as_float(f2tf(x));
        }
    }
}

__global__ void __launch_bounds__(THREADS, 1)
eve_fused_kernel(const float* __restrict__ z, const int* __restrict__ xs, const int* __restrict__ ys,
                 const float* __restrict__ W1, const float* __restrict__ b1,
                 const float* __restrict__ g1, const float* __restrict__ be1,
                 const float* __restrict__ W2, const float* __restrict__ b2,
                 const float* __restrict__ g2, const float* __restrict__ be2,
                 const float* __restrict__ Wh1, const float* __restrict__ bh1,
                 const float* __restrict__ Wh2, const float* __restrict__ bh2,
                 float* __restrict__ out)
{
    extern __shared__ float smem[];
    float* sh    = smem;                                  // 64*512 activations (col-swizzled)
    float* stage = smem + CTA_M * HID;                    // 2 * 9216-float chunk buffers
    float* sz    = stage + 2 * 2 * (HID / 8) * TILE_F;    // 64*64 z tile
    float* tbuf  = stage;                                 // reused for t[64][TSTRIDE]

    int tid = threadIdx.x;
    int cta_row = blockIdx.x * CTA_M;

    // load z tile, round to tf32, swizzle columns by row (one quad per thread)
    {
        int r = tid >> 4;
        int k = (tid & 15) << 2;
        float4 v = *reinterpret_cast<const float4*>(z + (size_t)(cta_row + r) * LAT + k);
        float4 w;
        w.x = __uint_as_float(f2tf(v.x));
        w.y = __uint_as_float(f2tf(v.y));
        w.z = __uint_as_float(f2tf(v.z));
        w.w = __uint_as_float(f2tf(v.w));
        *reinterpret_cast<float4*>(sz + r * LAT + (k ^ ((r & 7) << 2))) = w;
    }
    __syncthreads();

    float acc[8][4];

    // ---- encoder layer 1: h = leaky(LN(z @ W1 + b1)) ----
    run_gemm<512, 64, false>(sz, LAT, W1, stage, acc, tid);
    store_acc512(acc, sh, tid);
    __syncthreads();
    layernorm_leaky(sh, b1, g1, be1, tid);
    __syncthreads();

    // ---- encoder layer 2: h = leaky(LN(h @ W2 + b2)) ----
    run_gemm<512, 512, false>(sh, HID, W2, stage, acc, tid);
    store_acc512(acc, sh, tid);
    __syncthreads();
    layernorm_leaky(sh, b2, g2, be2, tid);
    __syncthreads();

    // ---- all 4 heads layer 1: t = relu(h @ Wh1_cat + bh1), N = 256 ----
    run_gemm<256, 512, true>(sh, HID, Wh1, stage, acc, tid);
    {
        int warp = tid >> 5, lane = tid & 31;
        int wm = warp & 1, wn = warp >> 1;
        int g = lane >> 2, t = lane & 3;
        #pragma unroll
        for (int mt = 0; mt < 2; mt++) {
            int row = wm * 32 + mt * 16 + g;
            #pragma unroll
            for (int nt = 0; nt < 2; nt++) {
                int col = wn * 16 + nt * 8 + 2 * t;
                float bb0 = __ldg(bh1 + col);
                float bb1 = __ldg(bh1 + col + 1);
                float* a = acc[mt * 2 + nt];
                tbuf[row * TSTRIDE + col]           = fmaxf(a[0] + bb0, 0.f);
                tbuf[row * TSTRIDE + col + 1]       = fmaxf(a[1] + bb1, 0.f);
                tbuf[(row + 8) * TSTRIDE + col]     = fmaxf(a[2] + bb0, 0.f);
                tbuf[(row + 8) * TSTRIDE + col + 1] = fmaxf(a[3] + bb1, 0.f);
            }
        }
    }
    __syncthreads();

    // ---- selected head layer 2 (64->4) + softmax, one thread per row ----
    if (tid < CTA_M) {
        int gr = cta_row + tid;
        int hk = 2 * __ldg(xs + gr) + __ldg(ys + gr);
        const float* w  = Wh2 + hk * (64 * 4);
        const float* tr = tbuf + tid * TSTRIDE + hk * 64;
        float4 bb = *reinterpret_cast<const float4*>(bh2 + hk * 4);
        float l0 = bb.x, l1 = bb.y, l2 = bb.z, l3 = bb.w;
        #pragma unroll 8
        for (int d = 0; d < 64; d++) {
            float tv = tr[d];
            float4 wv = __ldg(reinterpret_cast<const float4*>(w + d * 4));
            l0 = fmaf(tv, wv.x, l0);
            l1 = fmaf(tv, wv.y, l1);
            l2 = fmaf(tv, wv.z, l2);
            l3 = fmaf(tv, wv.w, l3);
        }
        float m = fmaxf(fmaxf(l0, l1), fmaxf(l2, l3));
        float e0 = expf(l0 - m), e1 = expf(l1 - m), e2 = expf(l2 - m), e3 = expf(l3 - m);
        float inv = 1.f / (e0 + e1 + e2 + e3);
        *reinterpret_cast<float4*>(out + (size_t)gr * 4) =
            make_float4(e0 * inv, e1 * inv, e2 * inv, e3 * inv);
    }
}

extern "C" void kernel_launch(void* const* d_in, const int* in_sizes, int n_in,
                              void* d_out, int out_size) {
    (void)n_in; (void)out_size;
    const float* z   = (const float*)d_in[0];
    const int*   xs  = (const int*)d_in[1];
    const int*   ys  = (const int*)d_in[2];
    const float* W1  = (const float*)d_in[3];
    const float* b1  = (const float*)d_in[4];
    const float* g1  = (const float*)d_in[5];
    const float* be1 = (const float*)d_in[6];
    const float* W2  = (const float*)d_in[7];
    const float* b2  = (const float*)d_in[8];
    const float* g2  = (const float*)d_in[9];
    const float* be2 = (const float*)d_in[10];
    const float* Wh1 = (const float*)d_in[11];
    const float* bh1 = (const float*)d_in[12];
    const float* Wh2 = (const float*)d_in[13];
    const float* bh2 = (const float*)d_in[14];
    float* out = (float*)d_out;

    int Btot = in_sizes[1];              // x has B elements
    int grid = Btot / CTA_M;
    // 32768 + 2*9216 + 4096 = 55296 floats = 221184 bytes
    size_t smem = (size_t)(CTA_M * HID + 2 * 2 * (HID / 8) * TILE_F + CTA_M * LAT) * sizeof(float);
    cudaFuncSetAttribute(eve_fused_kernel, cudaFuncAttributeMaxDynamicSharedMemorySize, (int)smem);
    eve_fused_kernel<<<grid, THREADS, smem>>>(z, xs, ys, W1, b1, g1, be1,
                                              W2, b2, g2, be2, Wh1, bh1, Wh2, bh2, out);
}

// round 13
// speedup vs baseline: 1.1573x; 1.1573x over previous
#include <cuda_runtime.h>

#define THREADS 512
#define CTA_M   64
#define HID     512
#define LAT     64
#define LNEPS   1e-5f
#define TSTRIDE 257

__device__ __forceinline__ unsigned f2tf(float f) {
    unsigned u;
    asm("cvt.rna.tf32.f32 %0, %1;" : "=r"(u) : "f"(f));
    return u;
}

__device__ __forceinline__ void mma8(float c[4], unsigned a0, unsigned a1, unsigned a2, unsigned a3,
                                     unsigned b0, unsigned b1) {
    asm volatile(
        "mma.sync.aligned.m16n8k8.row.col.f32.tf32.tf32.f32 "
        "{%0,%1,%2,%3},{%4,%5,%6,%7},{%8,%9},{%0,%1,%2,%3};\n"
        : "+f"(c[0]), "+f"(c[1]), "+f"(c[2]), "+f"(c[3])
        : "r"(a0), "r"(a1), "r"(a2), "r"(a3), "r"(b0), "r"(b1));
}

// load one k-step (8 rows) worth of B fragments straight from gmem (L2-hot).
// bp points at B[k + t][n0 + g]; nt tiles are 8 cols apart; b1 is 4 rows down.
template<int NT, int SN>
__device__ __forceinline__ void ldgB(float* b, const float* __restrict__ bp) {
    #pragma unroll
    for (int nt = 0; nt < NT; nt++) {
        b[2 * nt]     = __ldg(bp + nt * 8);
        b[2 * nt + 1] = __ldg(bp + nt * 8 + 4 * SN);
    }
}

// one k-step of mma: 8 A-frag LDS + 2*NT HMMAs
template<int NT>
__device__ __forceinline__ void mma_step(const float* arow0, const float* arow1,
                                         const float* arow2, const float* arow3,
                                         int s, int t, int sw, const float* b, float (*acc)[4]) {
    int k1 = (s * 8 + t) ^ sw;
    int k2 = (s * 8 + t + 4) ^ sw;
    unsigned a00 = __float_as_uint(arow0[k1]);
    unsigned a01 = __float_as_uint(arow1[k1]);
    unsigned a02 = __float_as_uint(arow0[k2]);
    unsigned a03 = __float_as_uint(arow1[k2]);
    unsigned a10 = __float_as_uint(arow2[k1]);
    unsigned a11 = __float_as_uint(arow3[k1]);
    unsigned a12 = __float_as_uint(arow2[k2]);
    unsigned a13 = __float_as_uint(arow3[k2]);
    #pragma unroll
    for (int nt = 0; nt < NT; nt++) {
        unsigned b0 = __float_as_uint(b[2 * nt]);
        unsigned b1 = __float_as_uint(b[2 * nt + 1]);
        mma8(acc[nt],      a00, a01, a02, a03, b0, b1);
        mma8(acc[NT + nt], a10, a11, a12, a13, b0, b1);
    }
}

// barrier-free GEMM mainloop: A from swizzled smem, B direct from L2,
// 2-deep register double buffer, one __syncthreads at the end.
template<int N, int KSTEPS, bool HEADS>
__device__ __forceinline__ void run_gemm(const float* Asm, int astride,
                                         const float* __restrict__ Bg,
                                         float (*acc)[4], int tid) {
    constexpr int NT = N / 64;          // n-tiles per warp (warp covers N/8 cols)
    constexpr int SN = HEADS ? 64 : N;  // row stride of weight matrix (floats)
    int warp = tid >> 5, lane = tid & 31;
    int wm = warp & 1, wn = warp >> 1;
    int g = lane >> 2, t = lane & 3;
    int sw = g << 2;
    #pragma unroll
    for (int i = 0; i < 2 * NT; i++) {
        #pragma unroll
        for (int j = 0; j < 4; j++) acc[i][j] = 0.f;
    }
    const float* bp;
    if (HEADS) bp = Bg + (wn >> 1) * (HID * 64) + t * 64 + (wn & 1) * 32 + g;
    else       bp = Bg + t * N + wn * 64 + g;
    const float* arow0 = Asm + (wm * 32 + g) * astride;
    const float* arow1 = arow0 + 8 * astride;
    const float* arow2 = arow0 + 16 * astride;
    const float* arow3 = arow0 + 24 * astride;

    float ba[2 * NT], bb[2 * NT];
    ldgB<NT, SN>(ba, bp);
    bp += 8 * SN;
    #pragma unroll 1
    for (int s = 0; s < KSTEPS; s += 2) {
        // step s: compute with ba, prefetch s+1 into bb
        ldgB<NT, SN>(bb, bp);
        bp += 8 * SN;
        mma_step<NT>(arow0, arow1, arow2, arow3, s, t, sw, ba, acc);
        // step s+1: compute with bb, prefetch s+2 into ba
        if (s + 2 < KSTEPS) {
            ldgB<NT, SN>(ba, bp);
            bp += 8 * SN;
        }
        mma_step<NT>(arow0, arow1, arow2, arow3, s + 1, t, sw, bb, acc);
    }
    __syncthreads();
}

// store whole-N accumulators (N=512) into swizzled activation buffer
__device__ __forceinline__ void store_acc512(float (*acc)[4], float* sh, int tid) {
    int warp = tid >> 5, lane = tid & 31;
    int wm = warp & 1, wn = warp >> 1;
    int g = lane >> 2, t = lane & 3;
    int s = g << 2;
    #pragma unroll
    for (int mt = 0; mt < 2; mt++) {
        int row = wm * 32 + mt * 16 + g;
        #pragma unroll
        for (int nt = 0; nt < 8; nt++) {
            int col = wn * 64 + nt * 8 + 2 * t;
            int c0 = col ^ s;   // swizzle leaves bits 0-1 intact (col even)
            float* a = acc[mt * 8 + nt];
            *reinterpret_cast<float2*>(sh + row * HID + c0)       = make_float2(a[0], a[1]);
            *reinterpret_cast<float2*>(sh + (row + 8) * HID + c0) = make_float2(a[2], a[3]);
        }
    }
}

// in-place: h = leaky( LN(h + bias) * gamma + beta ), output rounded to tf32
__device__ __forceinline__ void layernorm_leaky(float* sh, const float* __restrict__ bias,
                                                const float* __restrict__ gam,
                                                const float* __restrict__ bet, int tid) {
    int warp = tid >> 5, lane = tid & 31;
    float pb[16], pg[16], pe[16];
    #pragma unroll
    for (int j = 0; j < 16; j++) {
        int k = lane + 32 * j;
        pb[j] = __ldg(bias + k);
        pg[j] = __ldg(gam + k);
        pe[j] = __ldg(bet + k);
    }
    #pragma unroll 1
    for (int r0 = 0; r0 < 4; r0++) {
        int r = warp * 4 + r0;
        int s = (r & 7) << 2;
        float v[16];
        float sum = 0.f, sq = 0.f;
        #pragma unroll
        for (int j = 0; j < 16; j++) {
            int k = lane + 32 * j;
            float x = sh[r * HID + (k ^ s)] + pb[j];
            v[j] = x;
            sum += x;
            sq = fmaf(x, x, sq);
        }
        #pragma unroll
        for (int o = 16; o > 0; o >>= 1) {
            sum += __shfl_xor_sync(0xffffffffu, sum, o);
            sq  += __shfl_xor_sync(0xffffffffu, sq,  o);
        }
        float mu = sum * (1.f / 512.f);
        float var = sq * (1.f / 512.f) - mu * mu;
        float rs = rsqrtf(var + LNEPS);
        #pragma unroll
        for (int j = 0; j < 16; j++) {
            int k = lane + 32 * j;
            float x = (v[j] - mu) * rs * pg[j] + pe[j];
            x = (x >= 0.f) ? x : 0.2f * x;
            sh[r * HID + (k ^ s)] = __uint_as_float(f2tf(x));
        }
    }
}

__global__ void __launch_bounds__(THREADS, 1)
eve_fused_kernel(const float* __restrict__ z, const int* __restrict__ xs, const int* __restrict__ ys,
                 const float* __restrict__ W1, const float* __restrict__ b1,
                 const float* __restrict__ g1, const float* __restrict__ be1,
                 const float* __restrict__ W2, const float* __restrict__ b2,
                 const float* __restrict__ g2, const float* __restrict__ be2,
                 const float* __restrict__ Wh1, const float* __restrict__ bh1,
                 const float* __restrict__ Wh2, const float* __restrict__ bh2,
                 float* __restrict__ out)
{
    extern __shared__ float smem[];
    float* sh   = smem;                              // 64*512 activations (col-swizzled)
    float* sz   = sh + CTA_M * HID - CTA_M * LAT;    // z tile overlays sh tail
    float* tbuf = smem;                              // t[64][TSTRIDE] overlays sh after GEMM3

    int tid = threadIdx.x;
    int cta_row = blockIdx.x * CTA_M;

    // load z tile, round to tf32, swizzle columns by row
    #pragma unroll
    for (int i = 0; i < 2; i++) {
        int idx = tid + i * THREADS;
        int r = idx >> 4;
        int k = (idx & 15) << 2;
        float4 v = *reinterpret_cast<const float4*>(z + (size_t)(cta_row + r) * LAT + k);
        float4 w;
        w.x = __uint_as_float(f2tf(v.x));
        w.y = __uint_as_float(f2tf(v.y));
        w.z = __uint_as_float(f2tf(v.z));
        w.w = __uint_as_float(f2tf(v.w));
        *reinterpret_cast<float4*>(sz + r * LAT + (k ^ ((r & 7) << 2))) = w;
    }
    __syncthreads();

    float acc[16][4];

    // ---- encoder layer 1: h = leaky(LN(z @ W1 + b1)) ----
    run_gemm<512, 8, false>(sz, LAT, W1, acc, tid);
    store_acc512(acc, sh, tid);
    __syncthreads();
    layernorm_leaky(sh, b1, g1, be1, tid);
    __syncthreads();

    // ---- encoder layer 2: h = leaky(LN(h @ W2 + b2)) ----
    run_gemm<512, 64, false>(sh, HID, W2, acc, tid);
    store_acc512(acc, sh, tid);
    __syncthreads();
    layernorm_leaky(sh, b2, g2, be2, tid);
    __syncthreads();

    // ---- all 4 heads layer 1: t = relu(h @ Wh1_cat + bh1), N = 256 ----
    run_gemm<256, 64, true>(sh, HID, Wh1, acc, tid);
    {
        int warp = tid >> 5, lane = tid & 31;
        int wm = warp & 1, wn = warp >> 1;
        int g = lane >> 2, t = lane & 3;
        #pragma unroll
        for (int mt = 0; mt < 2; mt++) {
            int row = wm * 32 + mt * 16 + g;
            #pragma unroll
            for (int nt = 0; nt < 4; nt++) {
                int col = wn * 32 + nt * 8 + 2 * t;
                float bb0 = __ldg(bh1 + col);
                float bb1 = __ldg(bh1 + col + 1);
                float* a = acc[mt * 4 + nt];
                tbuf[row * TSTRIDE + col]           = fmaxf(a[0] + bb0, 0.f);
                tbuf[row * TSTRIDE + col + 1]       = fmaxf(a[1] + bb1, 0.f);
                tbuf[(row + 8) * TSTRIDE + col]     = fmaxf(a[2] + bb0, 0.f);
                tbuf[(row + 8) * TSTRIDE + col + 1] = fmaxf(a[3] + bb1, 0.f);
            }
        }
    }
    __syncthreads();

    // ---- selected head layer 2 (64->4) + softmax, one thread per row ----
    if (tid < CTA_M) {
        int gr = cta_row + tid;
        int hk = 2 * __ldg(xs + gr) + __ldg(ys + gr);
        const float* w  = Wh2 + hk * (64 * 4);
        const float* tr = tbuf + tid * TSTRIDE + hk * 64;
        float4 bb = *reinterpret_cast<const float4*>(bh2 + hk * 4);
        float l0 = bb.x, l1 = bb.y, l2 = bb.z, l3 = bb.w;
        #pragma unroll 8
        for (int d = 0; d < 64; d++) {
            float tv = tr[d];
            float4 wv = __ldg(reinterpret_cast<const float4*>(w + d * 4));
            l0 = fmaf(tv, wv.x, l0);
            l1 = fmaf(tv, wv.y, l1);
            l2 = fmaf(tv, wv.z, l2);
            l3 = fmaf(tv, wv.w, l3);
        }
        float m = fmaxf(fmaxf(l0, l1), fmaxf(l2, l3));
        float e0 = expf(l0 - m), e1 = expf(l1 - m), e2 = expf(l2 - m), e3 = expf(l3 - m);
        float inv = 1.f / (e0 + e1 + e2 + e3);
        *reinterpret_cast<float4*>(out + (size_t)gr * 4) =
            make_float4(e0 * inv, e1 * inv, e2 * inv, e3 * inv);
    }
}

extern "C" void kernel_launch(void* const* d_in, const int* in_sizes, int n_in,
                              void* d_out, int out_size) {
    (void)n_in; (void)out_size;
    const float* z   = (const float*)d_in[0];
    const int*   xs  = (const int*)d_in[1];
    const int*   ys  = (const int*)d_in[2];
    const float* W1  = (const float*)d_in[3];
    const float* b1  = (const float*)d_in[4];
    const float* g1  = (const float*)d_in[5];
    const float* be1 = (const float*)d_in[6];
    const float* W2  = (const float*)d_in[7];
    const float* b2  = (const float*)d_in[8];
    const float* g2  = (const float*)d_in[9];
    const float* be2 = (const float*)d_in[10];
    const float* Wh1 = (const float*)d_in[11];
    const float* bh1 = (const float*)d_in[12];
    const float* Wh2 = (const float*)d_in[13];
    const float* bh2 = (const float*)d_in[14];
    float* out = (float*)d_out;

    int Btot = in_sizes[1];              // x has B elements
    int grid = Btot / CTA_M;
    size_t smem = (size_t)(CTA_M * HID) * sizeof(float);   // 131072 bytes
    cudaFuncSetAttribute(eve_fused_kernel, cudaFuncAttributeMaxDynamicSharedMemorySize, (int)smem);
    eve_fused_kernel<<<grid, THREADS, smem>>>(z, xs, ys, W1, b1, g1, be1,
                                              W2, b2, g2, be2, Wh1, bh1, Wh2, bh2, out);
}

// round 16
// speedup vs baseline: 1.3114x; 1.1331x over previous
#include <cuda_runtime.h>

#define THREADS 512
#define CTA_M   64
#define KT      16
#define HID     512
#define LAT     64
#define LNEPS   1e-5f
#define TSTRIDE 257
#define TILE_F  72   // 64-float 8x8 tile + 8 pad: conflict-free stores AND loads

__device__ __forceinline__ unsigned f2tf(float f) {
    unsigned u;
    asm("cvt.rna.tf32.f32 %0, %1;" : "=r"(u) : "f"(f));
    return u;
}

__device__ __forceinline__ void mma8(float c[4], unsigned a0, unsigned a1, unsigned a2, unsigned a3,
                                     unsigned b0, unsigned b1) {
    asm volatile(
        "mma.sync.aligned.m16n8k8.row.col.f32.tf32.tf32.f32 "
        "{%0,%1,%2,%3},{%4,%5,%6,%7},{%8,%9},{%0,%1,%2,%3};\n"
        : "+f"(c[0]), "+f"(c[1]), "+f"(c[2]), "+f"(c[3])
        : "r"(a0), "r"(a1), "r"(a2), "r"(a3), "r"(b0), "r"(b1));
}

// ---- weight staging: each thread loads rows (k, k+4) x one n-quad ----
// chunk smem layout: 8x8 tiles of TILE_F floats; element (kp, nc) at
//   pos = (kp&1)*16 + ((kp>>1)&1)*8 + nc + (kp>=4 ? 32 : 0)
// b-frag reads (b0: kp=t, b1: kp=t+4) and STS.128 stores both conflict-free.
// Weights are stored as raw fp32: the HMMA unit truncates to tf32 in HW
// (measured rel_err 2.34e-4 in R6/R12/R13 — well under 1e-3).
template<int N, bool HEADS>
__device__ __forceinline__ void ldg_chunk(float4 (*pf)[2], const float* __restrict__ Bg, int k0, int tid) {
    constexpr int IT = N / 256;
    int w = tid >> 5, lane = tid & 31;
    int kstep = w & 1, kr = (w >> 1) & 3, half = w >> 3;
    int rA = k0 + kstep * 8 + kr;
    #pragma unroll
    for (int i = 0; i < IT; i++) {
        int nq = half * (IT * 32) + i * 32 + lane;
        int n = nq << 2;
        const float* pA;
        const float* pB;
        if (HEADS) {  // Wh1[4][HID][64], col n = head*64 + d
            pA = Bg + (n >> 6) * (HID * 64) + rA * 64 + (n & 63);
            pB = pA + 4 * 64;
        } else {
            pA = Bg + rA * N + n;
            pB = pA + 4 * N;
        }
        pf[i][0] = *reinterpret_cast<const float4*>(pA);
        pf[i][1] = *reinterpret_cast<const float4*>(pB);
    }
}

template<int N>
__device__ __forceinline__ void sts_chunk(const float4 (*pf)[2], float* buf, int tid) {
    constexpr int IT = N / 256;
    int w = tid >> 5, lane = tid & 31;
    int kstep = w & 1, kr = (w >> 1) & 3, half = w >> 3;
    #pragma unroll
    for (int i = 0; i < IT; i++) {
        int nq = half * (IT * 32) + i * 32 + lane;
        int nt = nq >> 1, ncb = nq & 1;
        float* tb = buf + (kstep * (N / 8) + nt) * TILE_F
                        + (kr & 1) * 16 + ((kr >> 1) & 1) * 8 + ncb * 4;
        *reinterpret_cast<float4*>(tb)      = pf[i][0];   // rows k   (kp = kr)
        *reinterpret_cast<float4*>(tb + 32) = pf[i][1];   // rows k+4 (kp = kr+4)
    }
}

// ---- mma over one staged chunk; warp = 2 m-tiles x (N/64) n-tiles ----
template<int N>
__device__ __forceinline__ void mma_chunk(const float* Asm, int astride, const float* buf,
                                          float (*acc)[4], int wm, int wn, int lane, int k0) {
    constexpr int NT = N / 64;
    int g = lane >> 2, t = lane & 3;
    int s = g << 2;
    int bpos = (t & 1) * 16 + (t >> 1) * 8 + g;   // matches sts_chunk layout
    #pragma unroll
    for (int ks = 0; ks < 2; ks++) {
        int kA = k0 + ks * 8 + t;
        unsigned a[2][4];
        #pragma unroll
        for (int mt = 0; mt < 2; mt++) {
            int row = wm * 32 + mt * 16 + g;
            a[mt][0] = __float_as_uint(Asm[row * astride + (kA ^ s)]);
            a[mt][1] = __float_as_uint(Asm[(row + 8) * astride + (kA ^ s)]);
            a[mt][2] = __float_as_uint(Asm[row * astride + ((kA + 4) ^ s)]);
            a[mt][3] = __float_as_uint(Asm[(row + 8) * astride + ((kA + 4) ^ s)]);
        }
        const float* tb = buf + (ks * (N / 8) + wn * NT) * TILE_F;
        #pragma unroll
        for (int nt = 0; nt < NT; nt++) {
            const float* tp = tb + nt * TILE_F;
            unsigned b0 = __float_as_uint(tp[bpos]);
            unsigned b1 = __float_as_uint(tp[bpos + 32]);
            mma8(acc[nt],      a[0][0], a[0][1], a[0][2], a[0][3], b0, b1);
            mma8(acc[NT + nt], a[1][0], a[1][1], a[1][2], a[1][3], b0, b1);
        }
    }
}

template<int N, int KTOT, bool HEADS>
__device__ __forceinline__ void run_gemm(const float* Asm, int astride, const float* __restrict__ Bg,
                                         float* stage, float (*acc)[4], int tid) {
    constexpr int NC = KTOT / KT;
    constexpr int NT2 = 2 * (N / 64);
    constexpr int CHUNKF = 2 * (N / 8) * TILE_F;
    int warp = tid >> 5, lane = tid & 31;
    int wm = warp & 1, wn = warp >> 1;
    #pragma unroll
    for (int i = 0; i < NT2; i++) {
        #pragma unroll
        for (int j = 0; j < 4; j++) acc[i][j] = 0.f;
    }
    float4 pf[2][2];
    ldg_chunk<N, HEADS>(pf, Bg, 0, tid);
    sts_chunk<N>(pf, stage, tid);
    __syncthreads();
    #pragma unroll 1
    for (int c = 0; c < NC; c++) {
        if (c + 1 < NC) ldg_chunk<N, HEADS>(pf, Bg, (c + 1) * KT, tid);
        mma_chunk<N>(Asm, astride, stage + (c & 1) * CHUNKF, acc, wm, wn, lane, c * KT);
        if (c + 1 < NC) sts_chunk<N>(pf, stage + ((c + 1) & 1) * CHUNKF, tid);
        __syncthreads();
    }
}

// store whole-N accumulators (N=512) into swizzled activation buffer
__device__ __forceinline__ void store_acc512(float (*acc)[4], float* sh, int tid) {
    int warp = tid >> 5, lane = tid & 31;
    int wm = warp & 1, wn = warp >> 1;
    int g = lane >> 2, t = lane & 3;
    int s = g << 2;
    #pragma unroll
    for (int mt = 0; mt < 2; mt++) {
        int row = wm * 32 + mt * 16 + g;
        #pragma unroll
        for (int nt = 0; nt < 8; nt++) {
            int col = wn * 64 + nt * 8 + 2 * t;
            int c0 = col ^ s;   // swizzle doesn't touch bit0/1 (col even), pair contiguous
            float* a = acc[mt * 8 + nt];
            *reinterpret_cast<float2*>(sh + row * HID + c0)       = make_float2(a[0], a[1]);
            *reinterpret_cast<float2*>(sh + (row + 8) * HID + c0) = make_float2(a[2], a[3]);
        }
    }
}

// in-place: h = leaky( LN(h + bias) * gamma + beta ), output rounded to tf32
__device__ __forceinline__ void layernorm_leaky(float* sh, const float* __restrict__ bias,
                                                const float* __restrict__ gam,
                                                const float* __restrict__ bet, int tid) {
    int warp = tid >> 5, lane = tid & 31;
    float pb[16], pg[16], pe[16];
    #pragma unroll
    for (int j = 0; j < 16; j++) {
        int k = lane + 32 * j;
        pb[j] = __ldg(bias + k);
        pg[j] = __ldg(gam + k);
        pe[j] = __ldg(bet + k);
    }
    #pragma unroll 1
    for (int r0 = 0; r0 < 4; r0++) {
        int r = warp * 4 + r0;
        int s = (r & 7) << 2;
        float v[16];
        float sum = 0.f, sq = 0.f;
        #pragma unroll
        for (int j = 0; j < 16; j++) {
            int k = lane + 32 * j;
            float x = sh[r * HID + (k ^ s)] + pb[j];
            v[j] = x;
            sum += x;
            sq = fmaf(x, x, sq);
        }
        #pragma unroll
        for (int o = 16; o > 0; o >>= 1) {
            sum += __shfl_xor_sync(0xffffffffu, sum, o);
            sq  += __shfl_xor_sync(0xffffffffu, sq,  o);
        }
        float mu = sum * (1.f / 512.f);
        float var = sq * (1.f / 512.f) - mu * mu;
        float rs = rsqrtf(var + LNEPS);
        #pragma unroll
        for (int j = 0; j < 16; j++) {
            int k = lane + 32 * j;
            float x = (v[j] - mu) * rs * pg[j] + pe[j];
            x = (x >= 0.f) ? x : 0.2f * x;
            sh[r * HID + (k ^ s)] = __uint_as_float(f2tf(x));
        }
    }
}

__global__ void __launch_bounds__(THREADS, 1)
eve_fused_kernel(const float* __restrict__ z, const int* __restrict__ xs, const int* __restrict__ ys,
                 const float* __restrict__ W1, const float* __restrict__ b1,
                 const float* __restrict__ g1, const float* __restrict__ be1,
                 const float* __restrict__ W2, const float* __restrict__ b2,
                 const float* __restrict__ g2, const float* __restrict__ be2,
                 const float* __restrict__ Wh1, const float* __restrict__ bh1,
                 const float* __restrict__ Wh2, const float* __restrict__ bh2,
                 float* __restrict__ out)
{
    extern __shared__ float smem[];
    float* sh    = smem;                                  // 64*512 activations (col-swizzled)
    float* stage = smem + CTA_M * HID;                    // 2 * 9216 weight chunk buffers
    float* sz    = stage + 2 * 2 * (HID / 8) * TILE_F;    // 64*64 z tile
    float* tbuf  = stage;                                 // reused for t[64][TSTRIDE]

    int tid = threadIdx.x;
    int cta_row = blockIdx.x * CTA_M;

    // load z tile, round to tf32, swizzle columns by row
    #pragma unroll
    for (int i = 0; i < 2; i++) {
        int idx = tid + i * THREADS;
        int r = idx >> 4;
        int k = (idx & 15) << 2;
        float4 v = *reinterpret_cast<const float4*>(z + (size_t)(cta_row + r) * LAT + k);
        float4 w;
        w.x = __uint_as_float(f2tf(v.x));
        w.y = __uint_as_float(f2tf(v.y));
        w.z = __uint_as_float(f2tf(v.z));
        w.w = __uint_as_float(f2tf(v.w));
        *reinterpret_cast<float4*>(sz + r * LAT + (k ^ ((r & 7) << 2))) = w;
    }
    __syncthreads();

    float acc[16][4];

    // ---- encoder layer 1: h = leaky(LN(z @ W1 + b1)) ----
    run_gemm<512, 64, false>(sz, LAT, W1, stage, acc, tid);
    store_acc512(acc, sh, tid);
    __syncthreads();
    layernorm_leaky(sh, b1, g1, be1, tid);
    __syncthreads();

    // ---- encoder layer 2: h = leaky(LN(h @ W2 + b2)) ----
    run_gemm<512, 512, false>(sh, HID, W2, stage, acc, tid);
    store_acc512(acc, sh, tid);
    __syncthreads();
    layernorm_leaky(sh, b2, g2, be2, tid);
    __syncthreads();

    // ---- all 4 heads layer 1: t = relu(h @ Wh1_cat + bh1), N = 256 ----
    run_gemm<256, 512, true>(sh, HID, Wh1, stage, acc, tid);
    {
        int warp = tid >> 5, lane = tid & 31;
        int wm = warp & 1, wn = warp >> 1;
        int g = lane >> 2, t = lane & 3;
        #pragma unroll
        for (int mt = 0; mt < 2; mt++) {
            int row = wm * 32 + mt * 16 + g;
            #pragma unroll
            for (int nt = 0; nt < 4; nt++) {
                int col = wn * 32 + nt * 8 + 2 * t;
                float bb0 = __ldg(bh1 + col);
                float bb1 = __ldg(bh1 + col + 1);
                float* a = acc[mt * 4 + nt];
                tbuf[row * TSTRIDE + col]           = fmaxf(a[0] + bb0, 0.f);
                tbuf[row * TSTRIDE + col + 1]       = fmaxf(a[1] + bb1, 0.f);
                tbuf[(row + 8) * TSTRIDE + col]     = fmaxf(a[2] + bb0, 0.f);
                tbuf[(row + 8) * TSTRIDE + col + 1] = fmaxf(a[3] + bb1, 0.f);
            }
        }
    }
    __syncthreads();

    // ---- selected head layer 2 (64->4) + softmax, one thread per row ----
    if (tid < CTA_M) {
        int gr = cta_row + tid;
        int hk = 2 * __ldg(xs + gr) + __ldg(ys + gr);
        const float* w  = Wh2 + hk * (64 * 4);
        const float* tr = tbuf + tid * TSTRIDE + hk * 64;
        float4 bb = *reinterpret_cast<const float4*>(bh2 + hk * 4);
        float l0 = bb.x, l1 = bb.y, l2 = bb.z, l3 = bb.w;
        #pragma unroll 8
        for (int d = 0; d < 64; d++) {
            float tv = tr[d];
            float4 wv = __ldg(reinterpret_cast<const float4*>(w + d * 4));
            l0 = fmaf(tv, wv.x, l0);
            l1 = fmaf(tv, wv.y, l1);
            l2 = fmaf(tv, wv.z, l2);
            l3 = fmaf(tv, wv.w, l3);
        }
        float m = fmaxf(fmaxf(l0, l1), fmaxf(l2, l3));
        float e0 = expf(l0 - m), e1 = expf(l1 - m), e2 = expf(l2 - m), e3 = expf(l3 - m);
        float inv = 1.f / (e0 + e1 + e2 + e3);
        *reinterpret_cast<float4*>(out + (size_t)gr * 4) =
            make_float4(e0 * inv, e1 * inv, e2 * inv, e3 * inv);
    }
}

extern "C" void kernel_launch(void* const* d_in, const int* in_sizes, int n_in,
                              void* d_out, int out_size) {
    (void)n_in; (void)out_size;
    const float* z   = (const float*)d_in[0];
    const int*   xs  = (const int*)d_in[1];
    const int*   ys  = (const int*)d_in[2];
    const float* W1  = (const float*)d_in[3];
    const float* b1  = (const float*)d_in[4];
    const float* g1  = (const float*)d_in[5];
    const float* be1 = (const float*)d_in[6];
    const float* W2  = (const float*)d_in[7];
    const float* b2  = (const float*)d_in[8];
    const float* g2  = (const float*)d_in[9];
    const float* be2 = (const float*)d_in[10];
    const float* Wh1 = (const float*)d_in[11];
    const float* bh1 = (const float*)d_in[12];
    const float* Wh2 = (const float*)d_in[13];
    const float* bh2 = (const float*)d_in[14];
    float* out = (float*)d_out;

    int Btot = in_sizes[1];              // x has B elements
    int grid = Btot / CTA_M;
    // 32768 + 2*9216 + 4096 = 55296 floats = 221184 bytes
    size_t smem = (size_t)(CTA_M * HID + 2 * 2 * (HID / 8) * TILE_F + CTA_M * LAT) * sizeof(float);
    cudaFuncSetAttribute(eve_fused_kernel, cudaFuncAttributeMaxDynamicSharedMemorySize, (int)smem);
    eve_fused_kernel<<<grid, THREADS, smem>>>(z, xs, ys, W1, b1, g1, be1,
                                              W2, b2, g2, be2, Wh1, bh1, Wh2, bh2, out);
}

// round 17
// speedup vs baseline: 1.3129x; 1.0012x over previous
#include <cuda_runtime.h>

#define THREADS 512
#define CTA_M   64
#define KT      16
#define HID     512
#define LAT     64
#define LNEPS   1e-5f
#define TSTRIDE 257
#define TILE_F  68   // 64-float pair-tile + 4 pad: stride 4 mod 32 -> conflict-free STS.64 and LDS.64

__device__ __forceinline__ unsigned f2tf(float f) {
    unsigned u;
    asm("cvt.rna.tf32.f32 %0, %1;" : "=r"(u) : "f"(f));
    return u;
}

__device__ __forceinline__ void mma8(float c[4], unsigned a0, unsigned a1, unsigned a2, unsigned a3,
                                     unsigned b0, unsigned b1) {
    asm volatile(
        "mma.sync.aligned.m16n8k8.row.col.f32.tf32.tf32.f32 "
        "{%0,%1,%2,%3},{%4,%5,%6,%7},{%8,%9},{%0,%1,%2,%3};\n"
        : "+f"(c[0]), "+f"(c[1]), "+f"(c[2]), "+f"(c[3])
        : "r"(a0), "r"(a1), "r"(a2), "r"(a3), "r"(b0), "r"(b1));
}

// pair-position: pair (k2 in 0..3, n in 0..7) stored at word 2*PQ(k2,n).
// The (n>>2) term makes n -> n+4 move by 32±2 words (not exactly 32),
// which is what keeps the STS.64 store pattern conflict-free.
__device__ __forceinline__ int PQ(int k2, int n) {
    return n * 4 + ((k2 + n + (n >> 2)) & 3);
}

// ---- weight staging: each thread loads rows (k, k+4) x one n-quad ----
// (identical coalesced LDG lane mapping to the R16 winner)
template<int N, bool HEADS>
__device__ __forceinline__ void ldg_chunk(float4 (*pf)[2], const float* __restrict__ Bg, int k0, int tid) {
    constexpr int IT = N / 256;
    int w = tid >> 5, lane = tid & 31;
    int kstep = w & 1, kr = (w >> 1) & 3, half = w >> 3;
    int rA = k0 + kstep * 8 + kr;
    #pragma unroll
    for (int i = 0; i < IT; i++) {
        int nq = half * (IT * 32) + i * 32 + lane;
        int n = nq << 2;
        const float* pA;
        const float* pB;
        if (HEADS) {  // Wh1[4][HID][64], col n = head*64 + d
            pA = Bg + (n >> 6) * (HID * 64) + rA * 64 + (n & 63);
            pB = pA + 4 * 64;
        } else {
            pA = Bg + rA * N + n;
            pB = pA + 4 * N;
        }
        pf[i][0] = *reinterpret_cast<const float4*>(pA);
        pf[i][1] = *reinterpret_cast<const float4*>(pB);
    }
}

// store pairs {row k, row k+4} adjacent: 4 STS.64 per (i), conflict-free with TILE_F=68
template<int N>
__device__ __forceinline__ void sts_chunk(const float4 (*pf)[2], float* buf, int tid) {
    constexpr int IT = N / 256;
    int w = tid >> 5, lane = tid & 31;
    int kstep = w & 1, kr = (w >> 1) & 3, half = w >> 3;
    #pragma unroll
    for (int i = 0; i < IT; i++) {
        int nq = half * (IT * 32) + i * 32 + lane;
        int nt = nq >> 1;
        int nb = (nq & 1) * 4;
        float* tb = buf + (kstep * (N / 8) + nt) * TILE_F;
        const float* v = reinterpret_cast<const float*>(&pf[i][0]);
        const float* u = reinterpret_cast<const float*>(&pf[i][1]);
        #pragma unroll
        for (int m = 0; m < 4; m++) {
            *reinterpret_cast<float2*>(tb + 2 * PQ(kr, nb + m)) = make_float2(v[m], u[m]);
        }
    }
}

// ---- mma over one staged chunk; warp = 2 m-tiles x (N/64) n-tiles ----
template<int N>
__device__ __forceinline__ void mma_chunk(const float* Asm, int astride, const float* buf,
                                          float (*acc)[4], int wm, int wn, int lane, int k0) {
    constexpr int NT = N / 64;
    int g = lane >> 2, t = lane & 3;
    int s = g << 2;
    int bofs = 2 * PQ(t, g);      // matches sts_chunk pair layout
    #pragma unroll
    for (int ks = 0; ks < 2; ks++) {
        int kA = k0 + ks * 8 + t;
        unsigned a[2][4];
        #pragma unroll
        for (int mt = 0; mt < 2; mt++) {
            int row = wm * 32 + mt * 16 + g;
            a[mt][0] = __float_as_uint(Asm[row * astride + (kA ^ s)]);
            a[mt][1] = __float_as_uint(Asm[(row + 8) * astride + (kA ^ s)]);
            a[mt][2] = __float_as_uint(Asm[row * astride + ((kA + 4) ^ s)]);
            a[mt][3] = __float_as_uint(Asm[(row + 8) * astride + ((kA + 4) ^ s)]);
        }
        const float* tb = buf + (ks * (N / 8) + wn * NT) * TILE_F;
        #pragma unroll
        for (int nt = 0; nt < NT; nt++) {
            float2 b = *reinterpret_cast<const float2*>(tb + nt * TILE_F + bofs);
            unsigned b0 = __float_as_uint(b.x);
            unsigned b1 = __float_as_uint(b.y);
            mma8(acc[nt],      a[0][0], a[0][1], a[0][2], a[0][3], b0, b1);
            mma8(acc[NT + nt], a[1][0], a[1][1], a[1][2], a[1][3], b0, b1);
        }
    }
}

template<int N, int KTOT, bool HEADS>
__device__ __forceinline__ void run_gemm(const float* Asm, int astride, const float* __restrict__ Bg,
                                         float* stage, float (*acc)[4], int tid) {
    constexpr int NC = KTOT / KT;
    constexpr int NT2 = 2 * (N / 64);
    constexpr int CHUNKF = 2 * (N / 8) * TILE_F;
    int warp = tid >> 5, lane = tid & 31;
    int wm = warp & 1, wn = warp >> 1;
    #pragma unroll
    for (int i = 0; i < NT2; i++) {
        #pragma unroll
        for (int j = 0; j < 4; j++) acc[i][j] = 0.f;
    }
    float4 pf[2][2];
    ldg_chunk<N, HEADS>(pf, Bg, 0, tid);
    sts_chunk<N>(pf, stage, tid);
    __syncthreads();
    #pragma unroll 1
    for (int c = 0; c < NC; c++) {
        if (c + 1 < NC) ldg_chunk<N, HEADS>(pf, Bg, (c + 1) * KT, tid);
        mma_chunk<N>(Asm, astride, stage + (c & 1) * CHUNKF, acc, wm, wn, lane, c * KT);
        if (c + 1 < NC) sts_chunk<N>(pf, stage + ((c + 1) & 1) * CHUNKF, tid);
        __syncthreads();
    }
}

// store whole-N accumulators (N=512) into swizzled activation buffer
__device__ __forceinline__ void store_acc512(float (*acc)[4], float* sh, int tid) {
    int warp = tid >> 5, lane = tid & 31;
    int wm = warp & 1, wn = warp >> 1;
    int g = lane >> 2, t = lane & 3;
    int s = g << 2;
    #pragma unroll
    for (int mt = 0; mt < 2; mt++) {
        int row = wm * 32 + mt * 16 + g;
        #pragma unroll
        for (int nt = 0; nt < 8; nt++) {
            int col = wn * 64 + nt * 8 + 2 * t;
            int c0 = col ^ s;
            float* a = acc[mt * 8 + nt];
            *reinterpret_cast<float2*>(sh + row * HID + c0)       = make_float2(a[0], a[1]);
            *reinterpret_cast<float2*>(sh + (row + 8) * HID + c0) = make_float2(a[2], a[3]);
        }
    }
}

// in-place: h = leaky( LN(h + bias) * gamma + beta ), output rounded to tf32
__device__ __forceinline__ void layernorm_leaky(float* sh, const float* __restrict__ bias,
                                                const float* __restrict__ gam,
                                                const float* __restrict__ bet, int tid) {
    int warp = tid >> 5, lane = tid & 31;
    float pb[16], pg[16], pe[16];
    #pragma unroll
    for (int j = 0; j < 16; j++) {
        int k = lane + 32 * j;
        pb[j] = __ldg(bias + k);
        pg[j] = __ldg(gam + k);
        pe[j] = __ldg(bet + k);
    }
    #pragma unroll 1
    for (int r0 = 0; r0 < 4; r0++) {
        int r = warp * 4 + r0;
        int s = (r & 7) << 2;
        float v[16];
        float sum = 0.f, sq = 0.f;
        #pragma unroll
        for (int j = 0; j < 16; j++) {
            int k = lane + 32 * j;
            float x = sh[r * HID + (k ^ s)] + pb[j];
            v[j] = x;
            sum += x;
            sq = fmaf(x, x, sq);
        }
        #pragma unroll
        for (int o = 16; o > 0; o >>= 1) {
            sum += __shfl_xor_sync(0xffffffffu, sum, o);
            sq  += __shfl_xor_sync(0xffffffffu, sq,  o);
        }
        float mu = sum * (1.f / 512.f);
        float var = sq * (1.f / 512.f) - mu * mu;
        float rs = rsqrtf(var + LNEPS);
        #pragma unroll
        for (int j = 0; j < 16; j++) {
            int k = lane + 32 * j;
            float x = (v[j] - mu) * rs * pg[j] + pe[j];
            x = (x >= 0.f) ? x : 0.2f * x;
            sh[r * HID + (k ^ s)] = __uint_as_float(f2tf(x));
        }
    }
}

__global__ void __launch_bounds__(THREADS, 1)
eve_fused_kernel(const float* __restrict__ z, const int* __restrict__ xs, const int* __restrict__ ys,
                 const float* __restrict__ W1, const float* __restrict__ b1,
                 const float* __restrict__ g1, const float* __restrict__ be1,
                 const float* __restrict__ W2, const float* __restrict__ b2,
                 const float* __restrict__ g2, const float* __restrict__ be2,
                 const float* __restrict__ Wh1, const float* __restrict__ bh1,
                 const float* __restrict__ Wh2, const float* __restrict__ bh2,
                 float* __restrict__ out)
{
    extern __shared__ float smem[];
    float* sh    = smem;                                  // 64*512 activations (col-swizzled)
    float* stage = smem + CTA_M * HID;                    // 2 * 8704 weight chunk buffers
    float* sz    = stage + 2 * 2 * (HID / 8) * TILE_F;    // 64*64 z tile
    float* tbuf  = stage;                                 // reused for t[64][TSTRIDE]

    int tid = threadIdx.x;
    int cta_row = blockIdx.x * CTA_M;

    // load z tile, round to tf32, swizzle columns by row
    #pragma unroll
    for (int i = 0; i < 2; i++) {
        int idx = tid + i * THREADS;
        int r = idx >> 4;
        int k = (idx & 15) << 2;
        float4 v = *reinterpret_cast<const float4*>(z + (size_t)(cta_row + r) * LAT + k);
        float4 w;
        w.x = __uint_as_float(f2tf(v.x));
        w.y = __uint_as_float(f2tf(v.y));
        w.z = __uint_as_float(f2tf(v.z));
        w.w = __uint_as_float(f2tf(v.w));
        *reinterpret_cast<float4*>(sz + r * LAT + (k ^ ((r & 7) << 2))) = w;
    }
    __syncthreads();

    float acc[16][4];

    // ---- encoder layer 1: h = leaky(LN(z @ W1 + b1)) ----
    run_gemm<512, 64, false>(sz, LAT, W1, stage, acc, tid);
    store_acc512(acc, sh, tid);
    __syncthreads();
    layernorm_leaky(sh, b1, g1, be1, tid);
    __syncthreads();

    // ---- encoder layer 2: h = leaky(LN(h @ W2 + b2)) ----
    run_gemm<512, 512, false>(sh, HID, W2, stage, acc, tid);
    store_acc512(acc, sh, tid);
    __syncthreads();
    layernorm_leaky(sh, b2, g2, be2, tid);
    __syncthreads();

    // ---- all 4 heads layer 1: t = relu(h @ Wh1_cat + bh1), N = 256 ----
    run_gemm<256, 512, true>(sh, HID, Wh1, stage, acc, tid);
    {
        int warp = tid >> 5, lane = tid & 31;
        int wm = warp & 1, wn = warp >> 1;
        int g = lane >> 2, t = lane & 3;
        #pragma unroll
        for (int mt = 0; mt < 2; mt++) {
            int row = wm * 32 + mt * 16 + g;
            #pragma unroll
            for (int nt = 0; nt < 4; nt++) {
                int col = wn * 32 + nt * 8 + 2 * t;
                float bb0 = __ldg(bh1 + col);
                float bb1 = __ldg(bh1 + col + 1);
                float* a = acc[mt * 4 + nt];
                tbuf[row * TSTRIDE + col]           = fmaxf(a[0] + bb0, 0.f);
                tbuf[row * TSTRIDE + col + 1]       = fmaxf(a[1] + bb1, 0.f);
                tbuf[(row + 8) * TSTRIDE + col]     = fmaxf(a[2] + bb0, 0.f);
                tbuf[(row + 8) * TSTRIDE + col + 1] = fmaxf(a[3] + bb1, 0.f);
            }
        }
    }
    __syncthreads();

    // ---- selected head layer 2 (64->4) + softmax, one thread per row ----
    if (tid < CTA_M) {
        int gr = cta_row + tid;
        int hk = 2 * __ldg(xs + gr) + __ldg(ys + gr);
        const float* w  = Wh2 + hk * (64 * 4);
        const float* tr = tbuf + tid * TSTRIDE + hk * 64;
        float4 bb = *reinterpret_cast<const float4*>(bh2 + hk * 4);
        float l0 = bb.x, l1 = bb.y, l2 = bb.z, l3 = bb.w;
        #pragma unroll 8
        for (int d = 0; d < 64; d++) {
            float tv = tr[d];
            float4 wv = __ldg(reinterpret_cast<const float4*>(w + d * 4));
            l0 = fmaf(tv, wv.x, l0);
            l1 = fmaf(tv, wv.y, l1);
            l2 = fmaf(tv, wv.z, l2);
            l3 = fmaf(tv, wv.w, l3);
        }
        float m = fmaxf(fmaxf(l0, l1), fmaxf(l2, l3));
        float e0 = expf(l0 - m), e1 = expf(l1 - m), e2 = expf(l2 - m), e3 = expf(l3 - m);
        float inv = 1.f / (e0 + e1 + e2 + e3);
        *reinterpret_cast<float4*>(out + (size_t)gr * 4) =
            make_float4(e0 * inv, e1 * inv, e2 * inv, e3 * inv);
    }
}

extern "C" void kernel_launch(void* const* d_in, const int* in_sizes, int n_in,
                              void* d_out, int out_size) {
    (void)n_in; (void)out_size;
    const float* z   = (const float*)d_in[0];
    const int*   xs  = (const int*)d_in[1];
    const int*   ys  = (const int*)d_in[2];
    const float* W1  = (const float*)d_in[3];
    const float* b1  = (const float*)d_in[4];
    const float* g1  = (const float*)d_in[5];
    const float* be1 = (const float*)d_in[6];
    const float* W2  = (const float*)d_in[7];
    const float* b2  = (const float*)d_in[8];
    const float* g2  = (const float*)d_in[9];
    const float* be2 = (const float*)d_in[10];
    const float* Wh1 = (const float*)d_in[11];
    const float* bh1 = (const float*)d_in[12];
    const float* Wh2 = (const float*)d_in[13];
    const float* bh2 = (const float*)d_in[14];
    float* out = (float*)d_out;

    int Btot = in_sizes[1];              // x has B elements
    int grid = Btot / CTA_M;
    // 32768 + 2*8704 + 4096 = 54272 floats = 217088 bytes
    size_t smem = (size_t)(CTA_M * HID + 2 * 2 * (HID / 8) * TILE_F + CTA_M * LAT) * sizeof(float);
    cudaFuncSetAttribute(eve_fused_kernel, cudaFuncAttributeMaxDynamicSharedMemorySize, (int)smem);
    eve_fused_kernel<<<grid, THREADS, smem>>>(z, xs, ys, W1, b1, g1, be1,
                                              W2, b2, g2, be2, Wh1, bh1, Wh2, bh2, out);
}